// round 11
// baseline (speedup 1.0000x reference)
#include <cuda_runtime.h>
#include <cuda_fp16.h>
#include <math.h>

// Batched log(A) for SPD 64x64, degree-23 Chebyshev via Paterson-Stockmeyer
// (s=3,k=8): 9 matmuls. R7: smem = Ah/Y (16K) + B (16K) + fp16 T2 (8K)
// -> 40KB/block -> 5 blocks/SM (10 warps). fp32 T2 lives in Bs for the one
// matmul that consumes it; epilogue-only operands (Ah, T2) are fp16.
// Inner loop uses immediate-offset LDS (fewer IADDs).

#define NN 64
#define KTERM 8
typedef unsigned long long ull;

__device__ __forceinline__ ull ffma2(ull a, ull b, ull c) {
    ull d;
    asm("fma.rn.f32x2 %0, %1, %2, %3;" : "=l"(d) : "l"(a), "l"(b), "l"(c));
    return d;
}
__device__ __forceinline__ ull dup2(float a) {
    ull d;
    asm("mov.b64 %0, {%1, %1};" : "=l"(d) : "f"(a));
    return d;
}
__device__ __forceinline__ void unpack2(ull v, float& lo, float& hi) {
    asm("mov.b64 {%0, %1}, %2;" : "=f"(lo), "=f"(hi) : "l"(v));
}
__device__ __forceinline__ ull pack2(float lo, float hi) {
    ull d;
    asm("mov.b64 %0, {%1, %2};" : "=l"(d) : "f"(lo), "f"(hi));
    return d;
}

// one kk step at literal byte offsets OA (A array) / OB (B array)
#define KKSTEP(OA, OB)                                                          \
    {                                                                           \
        float4 a0, a1;                                                          \
        asm("ld.shared.v4.f32 {%0,%1,%2,%3}, [%4+" #OA "];"                     \
            : "=f"(a0.x), "=f"(a0.y), "=f"(a0.z), "=f"(a0.w) : "r"(aA));        \
        asm("ld.shared.v4.f32 {%0,%1,%2,%3}, [%4+" #OA "+128];"                 \
            : "=f"(a1.x), "=f"(a1.y), "=f"(a1.z), "=f"(a1.w) : "r"(aA));        \
        ull b0, b1v, b2v, b3v;                                                  \
        asm("ld.shared.v2.u64 {%0,%1}, [%2+" #OB "];"                           \
            : "=l"(b0), "=l"(b1v) : "r"(bA));                                   \
        asm("ld.shared.v2.u64 {%0,%1}, [%2+" #OB "+128];"                       \
            : "=l"(b2v), "=l"(b3v) : "r"(bA));                                  \
        ull ad0 = dup2(a0.x), ad1 = dup2(a0.y), ad2 = dup2(a0.z), ad3 = dup2(a0.w); \
        ull ad4 = dup2(a1.x), ad5 = dup2(a1.y), ad6 = dup2(a1.z), ad7 = dup2(a1.w); \
        acc[0][0] = ffma2(ad0, b0, acc[0][0]);  acc[0][1] = ffma2(ad0, b1v, acc[0][1]); \
        acc[0][2] = ffma2(ad0, b2v, acc[0][2]); acc[0][3] = ffma2(ad0, b3v, acc[0][3]); \
        acc[1][0] = ffma2(ad1, b0, acc[1][0]);  acc[1][1] = ffma2(ad1, b1v, acc[1][1]); \
        acc[1][2] = ffma2(ad1, b2v, acc[1][2]); acc[1][3] = ffma2(ad1, b3v, acc[1][3]); \
        acc[2][0] = ffma2(ad2, b0, acc[2][0]);  acc[2][1] = ffma2(ad2, b1v, acc[2][1]); \
        acc[2][2] = ffma2(ad2, b2v, acc[2][2]); acc[2][3] = ffma2(ad2, b3v, acc[2][3]); \
        acc[3][0] = ffma2(ad3, b0, acc[3][0]);  acc[3][1] = ffma2(ad3, b1v, acc[3][1]); \
        acc[3][2] = ffma2(ad3, b2v, acc[3][2]); acc[3][3] = ffma2(ad3, b3v, acc[3][3]); \
        acc[4][0] = ffma2(ad4, b0, acc[4][0]);  acc[4][1] = ffma2(ad4, b1v, acc[4][1]); \
        acc[4][2] = ffma2(ad4, b2v, acc[4][2]); acc[4][3] = ffma2(ad4, b3v, acc[4][3]); \
        acc[5][0] = ffma2(ad5, b0, acc[5][0]);  acc[5][1] = ffma2(ad5, b1v, acc[5][1]); \
        acc[5][2] = ffma2(ad5, b2v, acc[5][2]); acc[5][3] = ffma2(ad5, b3v, acc[5][3]); \
        acc[6][0] = ffma2(ad6, b0, acc[6][0]);  acc[6][1] = ffma2(ad6, b1v, acc[6][1]); \
        acc[6][2] = ffma2(ad6, b2v, acc[6][2]); acc[6][3] = ffma2(ad6, b3v, acc[6][3]); \
        acc[7][0] = ffma2(ad7, b0, acc[7][0]);  acc[7][1] = ffma2(ad7, b1v, acc[7][1]); \
        acc[7][2] = ffma2(ad7, b2v, acc[7][2]); acc[7][3] = ffma2(ad7, b3v, acc[7][3]); \
    }

// acc = M * B over K=64, M symmetric (A-operand read via symmetry).
__device__ __forceinline__ void mm64(unsigned aA, unsigned bA, ull acc[8][4]) {
    #pragma unroll
    for (int ar = 0; ar < 8; ++ar)
        #pragma unroll
        for (int bp = 0; bp < 4; ++bp) acc[ar][bp] = 0ULL;
    #pragma unroll 4
    for (int kg = 0; kg < 16; ++kg) {
        KKSTEP(0, 0)
        KKSTEP(256, 256)
        KKSTEP(512, 512)
        KKSTEP(768, 768)
        aA += 1024;
        bA += 1024;
    }
}

__global__ __launch_bounds__(64, 5)
void logm_ps_kernel(const float* __restrict__ A, float* __restrict__ Out)
{
    extern __shared__ __align__(16) float sm[];
    float*  M0  = sm;                          // Ahat, later Y = T3
    float*  Bs  = sm + 4096;                   // fp32 T2, then Clenshaw b
    __half* T2h = (__half*)(sm + 8192);        // fp16 T2 (epilogue operand)
    float*  us  = sm + 10240;                  // 24 folded coefficients

    const int tid = threadIdx.x;
    const int mat = blockIdx.x;
    const int ti  = tid >> 3;
    const int tj  = tid & 7;

    const float lo  = 0.09f, hi = 5.30f;
    const float h   = 0.5f * (hi - lo);
    const float mid = 0.5f * (hi + lo);
    const float u   = mid / h;
    const float rho = u + sqrtf(u * u - 1.0f);
    const float alpha = 1.0f / h;

    // ---- Load A -> Ahat = alpha*A - u*I ----
    {
        const float4* Ag = (const float4*)(A + (size_t)mat * (NN * NN));
        #pragma unroll
        for (int r = 0; r < 16; ++r) {
            int q = tid + (r << 6);
            float4 v = Ag[q];
            int i = q >> 4;
            int j = (q & 15) << 2;
            v.x = alpha * v.x - ((j + 0 == i) ? u : 0.0f);
            v.y = alpha * v.y - ((j + 1 == i) ? u : 0.0f);
            v.z = alpha * v.z - ((j + 2 == i) ? u : 0.0f);
            v.w = alpha * v.w - ((j + 3 == i) ? u : 0.0f);
            *(float4*)(M0 + i * NN + j) = v;
        }
    }

    // ---- Thread 0: fold Chebyshev coeffs c_0..c_23 into u[i][j] ----
    if (tid == 0) {
        float d[3 * KTERM];
        d[0] = logf(h * rho * 0.5f);
        float rpw = 1.0f;
        const float ir = 1.0f / rho;
        #pragma unroll
        for (int m = 1; m < 3 * KTERM; ++m) {
            rpw *= ir;
            d[m] = ((m & 1) ? 2.0f : -2.0f) * rpw / (float)m;
        }
        #pragma unroll
        for (int i = KTERM - 1; i >= 1; --i) {
            us[3 * i + 2] = 2.0f * d[3 * i + 2];
            d[3 * i - 2] -= d[3 * i + 2];
            us[3 * i + 1] = 2.0f * d[3 * i + 1];
            d[3 * i - 1] -= d[3 * i + 1];
        }
        #pragma unroll
        for (int i = 1; i < KTERM; ++i) us[3 * i] = d[3 * i];
        us[0] = d[0];
        us[1] = d[1];
        us[2] = d[2];
    }
    __syncthreads();

    const unsigned sM0 = (unsigned)__cvta_generic_to_shared(M0);
    const unsigned sB  = (unsigned)__cvta_generic_to_shared(Bs);
    const unsigned oA  = (unsigned)(ti << 4);
    const unsigned oB  = (unsigned)(tj << 4);
    const int cA = tj << 2;
    const int cB = 32 + (tj << 2);

    // ---- Stash Ahat tile as half2 in registers (epilogue-only operand) ----
    __half2 ahr[8][4];
    #pragma unroll
    for (int ar = 0; ar < 8; ++ar) {
        const int row = ((ar & 4) << 3) + (ti << 2) + (ar & 3);
        float4 v0 = *(const float4*)(M0 + row * NN + cA);
        float4 v1 = *(const float4*)(M0 + row * NN + cB);
        ahr[ar][0] = __floats2half2_rn(v0.x, v0.y);
        ahr[ar][1] = __floats2half2_rn(v0.z, v0.w);
        ahr[ar][2] = __floats2half2_rn(v1.x, v1.y);
        ahr[ar][3] = __floats2half2_rn(v1.z, v1.w);
    }

    ull acc[8][4];

    // ---- Phase 1: T2 = 2*Ah*Ah - I  -> Bs (fp32) and T2h (fp16) ----
    mm64(sM0 + oA, sM0 + oB, acc);
    #pragma unroll
    for (int ar = 0; ar < 8; ++ar) {
        const int row = ((ar & 4) << 3) + (ti << 2) + (ar & 3);
        float a0, a1, a2, a3, a4, a5, a6, a7;
        unpack2(acc[ar][0], a0, a1); unpack2(acc[ar][1], a2, a3);
        unpack2(acc[ar][2], a4, a5); unpack2(acc[ar][3], a6, a7);
        float4 n0, n1;
        n0.x = 2.0f * a0 - ((row == cA + 0) ? 1.0f : 0.0f);
        n0.y = 2.0f * a1 - ((row == cA + 1) ? 1.0f : 0.0f);
        n0.z = 2.0f * a2 - ((row == cA + 2) ? 1.0f : 0.0f);
        n0.w = 2.0f * a3 - ((row == cA + 3) ? 1.0f : 0.0f);
        n1.x = 2.0f * a4 - ((row == cB + 0) ? 1.0f : 0.0f);
        n1.y = 2.0f * a5 - ((row == cB + 1) ? 1.0f : 0.0f);
        n1.z = 2.0f * a6 - ((row == cB + 2) ? 1.0f : 0.0f);
        n1.w = 2.0f * a7 - ((row == cB + 3) ? 1.0f : 0.0f);
        *(float4*)(Bs + row * NN + cA) = n0;
        *(float4*)(Bs + row * NN + cB) = n1;
        __half2* Th = (__half2*)(T2h + row * NN + cA);
        Th[0] = __floats2half2_rn(n0.x, n0.y);
        Th[1] = __floats2half2_rn(n0.z, n0.w);
        __half2* Th2 = (__half2*)(T2h + row * NN + cB);
        Th2[0] = __floats2half2_rn(n1.x, n1.y);
        Th2[1] = __floats2half2_rn(n1.z, n1.w);
    }
    __syncthreads();

    // ---- Phase 2: acc = Ah * T2 (T2 in Bs);  Y = 2*acc - Ah -> M0;
    //      U_7 = u0 I + u1 Ah + u2 T2 -> Bs (in place, own tile) ----
    mm64(sM0 + oA, sB + oB, acc);
    __syncthreads();               // all reads of M0 and Bs complete
    {
        const float u70 = us[3 * (KTERM - 1) + 0];
        const float u71 = us[3 * (KTERM - 1) + 1];
        const float u72 = us[3 * (KTERM - 1) + 2];
        #pragma unroll
        for (int ar = 0; ar < 8; ++ar) {
            const int row = ((ar & 4) << 3) + (ti << 2) + (ar & 3);
            float4 t20 = *(const float4*)(Bs + row * NN + cA);   // fp32 T2 own tile
            float4 t21 = *(const float4*)(Bs + row * NN + cB);
            float av[8];
            av[0] = __low2float(ahr[ar][0]); av[1] = __high2float(ahr[ar][0]);
            av[2] = __low2float(ahr[ar][1]); av[3] = __high2float(ahr[ar][1]);
            av[4] = __low2float(ahr[ar][2]); av[5] = __high2float(ahr[ar][2]);
            av[6] = __low2float(ahr[ar][3]); av[7] = __high2float(ahr[ar][3]);
            float a0, a1, a2, a3, a4, a5, a6, a7;
            unpack2(acc[ar][0], a0, a1); unpack2(acc[ar][1], a2, a3);
            unpack2(acc[ar][2], a4, a5); unpack2(acc[ar][3], a6, a7);
            float4 y0, y1;
            y0.x = 2.0f * a0 - av[0];  y0.y = 2.0f * a1 - av[1];
            y0.z = 2.0f * a2 - av[2];  y0.w = 2.0f * a3 - av[3];
            y1.x = 2.0f * a4 - av[4];  y1.y = 2.0f * a5 - av[5];
            y1.z = 2.0f * a6 - av[6];  y1.w = 2.0f * a7 - av[7];
            *(float4*)(M0 + row * NN + cA) = y0;
            *(float4*)(M0 + row * NN + cB) = y1;
            float4 b0, b1;
            b0.x = u71 * av[0] + u72 * t20.x + ((row == cA + 0) ? u70 : 0.0f);
            b0.y = u71 * av[1] + u72 * t20.y + ((row == cA + 1) ? u70 : 0.0f);
            b0.z = u71 * av[2] + u72 * t20.z + ((row == cA + 2) ? u70 : 0.0f);
            b0.w = u71 * av[3] + u72 * t20.w + ((row == cA + 3) ? u70 : 0.0f);
            b1.x = u71 * av[4] + u72 * t21.x + ((row == cB + 0) ? u70 : 0.0f);
            b1.y = u71 * av[5] + u72 * t21.y + ((row == cB + 1) ? u70 : 0.0f);
            b1.z = u71 * av[6] + u72 * t21.z + ((row == cB + 2) ? u70 : 0.0f);
            b1.w = u71 * av[7] + u72 * t21.w + ((row == cB + 3) ? u70 : 0.0f);
            *(float4*)(Bs + row * NN + cA) = b0;
            *(float4*)(Bs + row * NN + cB) = b1;
        }
    }
    ull b2t[8][4];
    #pragma unroll
    for (int ar = 0; ar < 8; ++ar)
        #pragma unroll
        for (int bp = 0; bp < 4; ++bp) b2t[ar][bp] = 0ULL;
    __syncthreads();

    // ---- Clenshaw in y: i = 6..1  (M0 holds Y; T2 via T2h fp16) ----
    for (int i = KTERM - 2; i >= 1; --i) {
        const float u0 = us[3 * i + 0];
        const float u1 = us[3 * i + 1];
        const float u2 = us[3 * i + 2];
        mm64(sM0 + oA, sB + oB, acc);
        __syncthreads();
        #pragma unroll
        for (int ar = 0; ar < 8; ++ar) {
            const int row = ((ar & 4) << 3) + (ti << 2) + (ar & 3);
            float* Bp = Bs + row * NN;
            float4 t0 = *(const float4*)(Bp + cA);     // old b1 -> next b2
            float4 t1 = *(const float4*)(Bp + cB);
            const __half2* ThA = (const __half2*)(T2h + row * NN + cA);
            const __half2* ThB = (const __half2*)(T2h + row * NN + cB);
            float2 q0 = __half22float2(ThA[0]);
            float2 q1 = __half22float2(ThA[1]);
            float2 q2 = __half22float2(ThB[0]);
            float2 q3 = __half22float2(ThB[1]);
            float av[8];
            av[0] = __low2float(ahr[ar][0]); av[1] = __high2float(ahr[ar][0]);
            av[2] = __low2float(ahr[ar][1]); av[3] = __high2float(ahr[ar][1]);
            av[4] = __low2float(ahr[ar][2]); av[5] = __high2float(ahr[ar][2]);
            av[6] = __low2float(ahr[ar][3]); av[7] = __high2float(ahr[ar][3]);
            float a0, a1, a2, a3, a4, a5, a6, a7;
            unpack2(acc[ar][0], a0, a1); unpack2(acc[ar][1], a2, a3);
            unpack2(acc[ar][2], a4, a5); unpack2(acc[ar][3], a6, a7);
            float o0, o1, o2, o3, o4, o5, o6, o7;
            unpack2(b2t[ar][0], o0, o1); unpack2(b2t[ar][1], o2, o3);
            unpack2(b2t[ar][2], o4, o5); unpack2(b2t[ar][3], o6, o7);
            float4 n0, n1;
            n0.x = 2.0f * a0 - o0 + u1 * av[0] + u2 * q0.x + ((row == cA + 0) ? u0 : 0.0f);
            n0.y = 2.0f * a1 - o1 + u1 * av[1] + u2 * q0.y + ((row == cA + 1) ? u0 : 0.0f);
            n0.z = 2.0f * a2 - o2 + u1 * av[2] + u2 * q1.x + ((row == cA + 2) ? u0 : 0.0f);
            n0.w = 2.0f * a3 - o3 + u1 * av[3] + u2 * q1.y + ((row == cA + 3) ? u0 : 0.0f);
            n1.x = 2.0f * a4 - o4 + u1 * av[4] + u2 * q2.x + ((row == cB + 0) ? u0 : 0.0f);
            n1.y = 2.0f * a5 - o5 + u1 * av[5] + u2 * q2.y + ((row == cB + 1) ? u0 : 0.0f);
            n1.z = 2.0f * a6 - o6 + u1 * av[6] + u2 * q3.x + ((row == cB + 2) ? u0 : 0.0f);
            n1.w = 2.0f * a7 - o7 + u1 * av[7] + u2 * q3.y + ((row == cB + 3) ? u0 : 0.0f);
            *(float4*)(Bp + cA) = n0;
            *(float4*)(Bp + cB) = n1;
            b2t[ar][0] = pack2(t0.x, t0.y);
            b2t[ar][1] = pack2(t0.z, t0.w);
            b2t[ar][2] = pack2(t1.x, t1.y);
            b2t[ar][3] = pack2(t1.z, t1.w);
        }
        __syncthreads();
    }

    // ---- Final: out = U_0 + y*b1 - b2 ----
    {
        const float u0 = us[0];
        const float u1 = us[1];
        const float u2 = us[2];
        mm64(sM0 + oA, sB + oB, acc);
        float* Og = Out + (size_t)mat * (NN * NN);
        #pragma unroll
        for (int ar = 0; ar < 8; ++ar) {
            const int row = ((ar & 4) << 3) + (ti << 2) + (ar & 3);
            const __half2* ThA = (const __half2*)(T2h + row * NN + cA);
            const __half2* ThB = (const __half2*)(T2h + row * NN + cB);
            float2 q0 = __half22float2(ThA[0]);
            float2 q1 = __half22float2(ThA[1]);
            float2 q2 = __half22float2(ThB[0]);
            float2 q3 = __half22float2(ThB[1]);
            float av[8];
            av[0] = __low2float(ahr[ar][0]); av[1] = __high2float(ahr[ar][0]);
            av[2] = __low2float(ahr[ar][1]); av[3] = __high2float(ahr[ar][1]);
            av[4] = __low2float(ahr[ar][2]); av[5] = __high2float(ahr[ar][2]);
            av[6] = __low2float(ahr[ar][3]); av[7] = __high2float(ahr[ar][3]);
            float a0, a1, a2, a3, a4, a5, a6, a7;
            unpack2(acc[ar][0], a0, a1); unpack2(acc[ar][1], a2, a3);
            unpack2(acc[ar][2], a4, a5); unpack2(acc[ar][3], a6, a7);
            float o0, o1, o2, o3, o4, o5, o6, o7;
            unpack2(b2t[ar][0], o0, o1); unpack2(b2t[ar][1], o2, o3);
            unpack2(b2t[ar][2], o4, o5); unpack2(b2t[ar][3], o6, o7);
            float4 n0, n1;
            n0.x = a0 - o0 + u1 * av[0] + u2 * q0.x + ((row == cA + 0) ? u0 : 0.0f);
            n0.y = a1 - o1 + u1 * av[1] + u2 * q0.y + ((row == cA + 1) ? u0 : 0.0f);
            n0.z = a2 - o2 + u1 * av[2] + u2 * q1.x + ((row == cA + 2) ? u0 : 0.0f);
            n0.w = a3 - o3 + u1 * av[3] + u2 * q1.y + ((row == cA + 3) ? u0 : 0.0f);
            n1.x = a4 - o4 + u1 * av[4] + u2 * q2.x + ((row == cB + 0) ? u0 : 0.0f);
            n1.y = a5 - o5 + u1 * av[5] + u2 * q2.y + ((row == cB + 1) ? u0 : 0.0f);
            n1.z = a6 - o6 + u1 * av[6] + u2 * q3.x + ((row == cB + 2) ? u0 : 0.0f);
            n1.w = a7 - o7 + u1 * av[7] + u2 * q3.y + ((row == cB + 3) ? u0 : 0.0f);
            *(float4*)(Og + row * NN + cA) = n0;
            *(float4*)(Og + row * NN + cB) = n1;
        }
    }
}

#define SMEM_BYTES ((10240 + 32) * 4)

extern "C" void kernel_launch(void* const* d_in, const int* in_sizes, int n_in,
                              void* d_out, int out_size) {
    const float* x = (const float*)d_in[0];
    float* out = (float*)d_out;
    int nmat = in_sizes[0] / (NN * NN);
    cudaFuncSetAttribute(logm_ps_kernel,
                         cudaFuncAttributeMaxDynamicSharedMemorySize, SMEM_BYTES);
    logm_ps_kernel<<<nmat, 64, SMEM_BYTES>>>(x, out);
}

// round 12
// speedup vs baseline: 1.3057x; 1.3057x over previous
#include <cuda_runtime.h>
#include <math.h>

// Batched log(A) for SPD 64x64, degree-20 Chebyshev via Paterson-Stockmeyer
// in the Chebyshev basis (s=3, k=7): 8 matmuls (T2, T3, 5 Clenshaw-in-y,
// final). R8 = R6 engine (known-good: 3 smem arrays, 48KB, 4 blocks/SM,
// 8x8 split register tiles, FFMA2) with KTERM 8 -> 7.

#define NN 64
#define KTERM 7
typedef unsigned long long ull;

__device__ __forceinline__ ull ffma2(ull a, ull b, ull c) {
    ull d;
    asm("fma.rn.f32x2 %0, %1, %2, %3;" : "=l"(d) : "l"(a), "l"(b), "l"(c));
    return d;
}
__device__ __forceinline__ ull dup2(float a) {
    ull d;
    asm("mov.b64 %0, {%1, %1};" : "=l"(d) : "f"(a));
    return d;
}
__device__ __forceinline__ void unpack2(ull v, float& lo, float& hi) {
    asm("mov.b64 {%0, %1}, %2;" : "=f"(lo), "=f"(hi) : "l"(v));
}
__device__ __forceinline__ ull pack2(float lo, float hi) {
    ull d;
    asm("mov.b64 %0, {%1, %2};" : "=l"(d) : "f"(lo), "f"(hi));
    return d;
}

// acc = M * B over K=64, M symmetric (A-operand read via symmetry).
__device__ __forceinline__ void mm64(unsigned aA, unsigned bA, ull acc[8][4]) {
    #pragma unroll
    for (int ar = 0; ar < 8; ++ar)
        #pragma unroll
        for (int bp = 0; bp < 4; ++bp) acc[ar][bp] = 0ULL;
    #pragma unroll 4
    for (int kk = 0; kk < NN; ++kk) {
        float4 a0, a1;
        asm("ld.shared.v4.f32 {%0,%1,%2,%3}, [%4];"
            : "=f"(a0.x), "=f"(a0.y), "=f"(a0.z), "=f"(a0.w) : "r"(aA));
        asm("ld.shared.v4.f32 {%0,%1,%2,%3}, [%4+128];"
            : "=f"(a1.x), "=f"(a1.y), "=f"(a1.z), "=f"(a1.w) : "r"(aA));
        ull b0, b1v, b2v, b3v;
        asm("ld.shared.v2.u64 {%0,%1}, [%2];"     : "=l"(b0),  "=l"(b1v) : "r"(bA));
        asm("ld.shared.v2.u64 {%0,%1}, [%2+128];" : "=l"(b2v), "=l"(b3v) : "r"(bA));
        ull ad[8];
        ad[0] = dup2(a0.x); ad[1] = dup2(a0.y); ad[2] = dup2(a0.z); ad[3] = dup2(a0.w);
        ad[4] = dup2(a1.x); ad[5] = dup2(a1.y); ad[6] = dup2(a1.z); ad[7] = dup2(a1.w);
        #pragma unroll
        for (int ar = 0; ar < 8; ++ar) {
            acc[ar][0] = ffma2(ad[ar], b0,  acc[ar][0]);
            acc[ar][1] = ffma2(ad[ar], b1v, acc[ar][1]);
            acc[ar][2] = ffma2(ad[ar], b2v, acc[ar][2]);
            acc[ar][3] = ffma2(ad[ar], b3v, acc[ar][3]);
        }
        aA += NN * 4;
        bA += NN * 4;
    }
}

__global__ __launch_bounds__(64, 4)
void logm_ps_kernel(const float* __restrict__ A, float* __restrict__ Out)
{
    extern __shared__ __align__(16) float sm[];
    float* M0 = sm;               // Ahat, later overwritten by Y = T3
    float* T2s = sm + 4096;       // T2(Ahat)
    float* Bs  = sm + 8192;       // Clenshaw b (in y)
    float* us  = sm + 12288;      // 21 folded coefficients

    const int tid = threadIdx.x;
    const int mat = blockIdx.x;
    const int ti  = tid >> 3;
    const int tj  = tid & 7;

    const float lo  = 0.09f, hi = 5.30f;
    const float h   = 0.5f * (hi - lo);
    const float mid = 0.5f * (hi + lo);
    const float u   = mid / h;
    const float rho = u + sqrtf(u * u - 1.0f);
    const float alpha = 1.0f / h;

    // ---- Load A -> Ahat = alpha*A - u*I ----
    {
        const float4* Ag = (const float4*)(A + (size_t)mat * (NN * NN));
        #pragma unroll
        for (int r = 0; r < 16; ++r) {
            int q = tid + (r << 6);
            float4 v = Ag[q];
            int i = q >> 4;
            int j = (q & 15) << 2;
            v.x = alpha * v.x - ((j + 0 == i) ? u : 0.0f);
            v.y = alpha * v.y - ((j + 1 == i) ? u : 0.0f);
            v.z = alpha * v.z - ((j + 2 == i) ? u : 0.0f);
            v.w = alpha * v.w - ((j + 3 == i) ? u : 0.0f);
            *(float4*)(M0 + i * NN + j) = v;
        }
    }

    // ---- Thread 0: fold Chebyshev coeffs c_0..c_20 into u[i][j] ----
    if (tid == 0) {
        float d[3 * KTERM];
        d[0] = logf(h * rho * 0.5f);
        float rpw = 1.0f;
        const float ir = 1.0f / rho;
        #pragma unroll
        for (int m = 1; m < 3 * KTERM; ++m) {
            rpw *= ir;
            d[m] = ((m & 1) ? 2.0f : -2.0f) * rpw / (float)m;
        }
        #pragma unroll
        for (int i = KTERM - 1; i >= 1; --i) {
            us[3 * i + 2] = 2.0f * d[3 * i + 2];
            d[3 * i - 2] -= d[3 * i + 2];
            us[3 * i + 1] = 2.0f * d[3 * i + 1];
            d[3 * i - 1] -= d[3 * i + 1];
        }
        #pragma unroll
        for (int i = 1; i < KTERM; ++i) us[3 * i] = d[3 * i];
        us[0] = d[0];
        us[1] = d[1];
        us[2] = d[2];
    }
    __syncthreads();

    const unsigned sM0 = (unsigned)__cvta_generic_to_shared(M0);
    const unsigned sT2 = (unsigned)__cvta_generic_to_shared(T2s);
    const unsigned sB  = (unsigned)__cvta_generic_to_shared(Bs);
    const unsigned oA  = (unsigned)(ti << 4);
    const unsigned oB  = (unsigned)(tj << 4);
    const int cA = tj << 2;
    const int cB = 32 + (tj << 2);

    // ---- Stash this thread's Ahat tile in registers (epilogue operand) ----
    float4 ahr[8][2];
    #pragma unroll
    for (int ar = 0; ar < 8; ++ar) {
        const int row = ((ar & 4) << 3) + (ti << 2) + (ar & 3);
        ahr[ar][0] = *(const float4*)(M0 + row * NN + cA);
        ahr[ar][1] = *(const float4*)(M0 + row * NN + cB);
    }

    ull acc[8][4];

    // ---- Phase 1: T2 = 2*Ah*Ah - I ----
    mm64(sM0 + oA, sM0 + oB, acc);
    #pragma unroll
    for (int ar = 0; ar < 8; ++ar) {
        const int row = ((ar & 4) << 3) + (ti << 2) + (ar & 3);
        float a0, a1, a2, a3, a4, a5, a6, a7;
        unpack2(acc[ar][0], a0, a1); unpack2(acc[ar][1], a2, a3);
        unpack2(acc[ar][2], a4, a5); unpack2(acc[ar][3], a6, a7);
        float4 n0, n1;
        n0.x = 2.0f * a0 - ((row == cA + 0) ? 1.0f : 0.0f);
        n0.y = 2.0f * a1 - ((row == cA + 1) ? 1.0f : 0.0f);
        n0.z = 2.0f * a2 - ((row == cA + 2) ? 1.0f : 0.0f);
        n0.w = 2.0f * a3 - ((row == cA + 3) ? 1.0f : 0.0f);
        n1.x = 2.0f * a4 - ((row == cB + 0) ? 1.0f : 0.0f);
        n1.y = 2.0f * a5 - ((row == cB + 1) ? 1.0f : 0.0f);
        n1.z = 2.0f * a6 - ((row == cB + 2) ? 1.0f : 0.0f);
        n1.w = 2.0f * a7 - ((row == cB + 3) ? 1.0f : 0.0f);
        *(float4*)(T2s + row * NN + cA) = n0;
        *(float4*)(T2s + row * NN + cB) = n1;
    }
    __syncthreads();

    // ---- Phase 2: acc = Ah*T2; then Y = 2*acc - Ah overwrites M0;
    //      B = U_{K-1} = u0 I + u1 Ah + u2 T2 ----
    mm64(sM0 + oA, sT2 + oB, acc);
    __syncthreads();               // all reads of M0 (Ah) complete before overwrite
    {
        const float u70 = us[3 * (KTERM - 1) + 0];
        const float u71 = us[3 * (KTERM - 1) + 1];
        const float u72 = us[3 * (KTERM - 1) + 2];
        #pragma unroll
        for (int ar = 0; ar < 8; ++ar) {
            const int row = ((ar & 4) << 3) + (ti << 2) + (ar & 3);
            float4 av0 = ahr[ar][0];
            float4 av1 = ahr[ar][1];
            float4 t20 = *(const float4*)(T2s + row * NN + cA);
            float4 t21 = *(const float4*)(T2s + row * NN + cB);
            float a0, a1, a2, a3, a4, a5, a6, a7;
            unpack2(acc[ar][0], a0, a1); unpack2(acc[ar][1], a2, a3);
            unpack2(acc[ar][2], a4, a5); unpack2(acc[ar][3], a6, a7);
            float4 y0, y1;
            y0.x = 2.0f * a0 - av0.x;  y0.y = 2.0f * a1 - av0.y;
            y0.z = 2.0f * a2 - av0.z;  y0.w = 2.0f * a3 - av0.w;
            y1.x = 2.0f * a4 - av1.x;  y1.y = 2.0f * a5 - av1.y;
            y1.z = 2.0f * a6 - av1.z;  y1.w = 2.0f * a7 - av1.w;
            *(float4*)(M0 + row * NN + cA) = y0;
            *(float4*)(M0 + row * NN + cB) = y1;
            float4 b0, b1;
            b0.x = u71 * av0.x + u72 * t20.x + ((row == cA + 0) ? u70 : 0.0f);
            b0.y = u71 * av0.y + u72 * t20.y + ((row == cA + 1) ? u70 : 0.0f);
            b0.z = u71 * av0.z + u72 * t20.z + ((row == cA + 2) ? u70 : 0.0f);
            b0.w = u71 * av0.w + u72 * t20.w + ((row == cA + 3) ? u70 : 0.0f);
            b1.x = u71 * av1.x + u72 * t21.x + ((row == cB + 0) ? u70 : 0.0f);
            b1.y = u71 * av1.y + u72 * t21.y + ((row == cB + 1) ? u70 : 0.0f);
            b1.z = u71 * av1.z + u72 * t21.z + ((row == cB + 2) ? u70 : 0.0f);
            b1.w = u71 * av1.w + u72 * t21.w + ((row == cB + 3) ? u70 : 0.0f);
            *(float4*)(Bs + row * NN + cA) = b0;
            *(float4*)(Bs + row * NN + cB) = b1;
        }
    }
    ull b2t[8][4];
    #pragma unroll
    for (int ar = 0; ar < 8; ++ar)
        #pragma unroll
        for (int bp = 0; bp < 4; ++bp) b2t[ar][bp] = 0ULL;
    __syncthreads();

    // ---- Clenshaw in y: i = KTERM-2..1  (M0 now holds Y) ----
    for (int i = KTERM - 2; i >= 1; --i) {
        const float u0 = us[3 * i + 0];
        const float u1 = us[3 * i + 1];
        const float u2 = us[3 * i + 2];
        mm64(sM0 + oA, sB + oB, acc);
        __syncthreads();
        #pragma unroll
        for (int ar = 0; ar < 8; ++ar) {
            const int row = ((ar & 4) << 3) + (ti << 2) + (ar & 3);
            float* Bp = Bs + row * NN;
            float4 t0 = *(const float4*)(Bp + cA);     // old b1 -> next b2
            float4 t1 = *(const float4*)(Bp + cB);
            float4 av0 = ahr[ar][0];
            float4 av1 = ahr[ar][1];
            float4 t20 = *(const float4*)(T2s + row * NN + cA);
            float4 t21 = *(const float4*)(T2s + row * NN + cB);
            float a0, a1, a2, a3, a4, a5, a6, a7;
            unpack2(acc[ar][0], a0, a1); unpack2(acc[ar][1], a2, a3);
            unpack2(acc[ar][2], a4, a5); unpack2(acc[ar][3], a6, a7);
            float o0, o1, o2, o3, o4, o5, o6, o7;
            unpack2(b2t[ar][0], o0, o1); unpack2(b2t[ar][1], o2, o3);
            unpack2(b2t[ar][2], o4, o5); unpack2(b2t[ar][3], o6, o7);
            float4 n0, n1;
            n0.x = 2.0f * a0 - o0 + u1 * av0.x + u2 * t20.x + ((row == cA + 0) ? u0 : 0.0f);
            n0.y = 2.0f * a1 - o1 + u1 * av0.y + u2 * t20.y + ((row == cA + 1) ? u0 : 0.0f);
            n0.z = 2.0f * a2 - o2 + u1 * av0.z + u2 * t20.z + ((row == cA + 2) ? u0 : 0.0f);
            n0.w = 2.0f * a3 - o3 + u1 * av0.w + u2 * t20.w + ((row == cA + 3) ? u0 : 0.0f);
            n1.x = 2.0f * a4 - o4 + u1 * av1.x + u2 * t21.x + ((row == cB + 0) ? u0 : 0.0f);
            n1.y = 2.0f * a5 - o5 + u1 * av1.y + u2 * t21.y + ((row == cB + 1) ? u0 : 0.0f);
            n1.z = 2.0f * a6 - o6 + u1 * av1.z + u2 * t21.z + ((row == cB + 2) ? u0 : 0.0f);
            n1.w = 2.0f * a7 - o7 + u1 * av1.w + u2 * t21.w + ((row == cB + 3) ? u0 : 0.0f);
            *(float4*)(Bp + cA) = n0;
            *(float4*)(Bp + cB) = n1;
            b2t[ar][0] = pack2(t0.x, t0.y);
            b2t[ar][1] = pack2(t0.z, t0.w);
            b2t[ar][2] = pack2(t1.x, t1.y);
            b2t[ar][3] = pack2(t1.z, t1.w);
        }
        __syncthreads();
    }

    // ---- Final: out = U_0 + y*b1 - b2 ----
    {
        const float u0 = us[0];
        const float u1 = us[1];
        const float u2 = us[2];
        mm64(sM0 + oA, sB + oB, acc);
        float* Og = Out + (size_t)mat * (NN * NN);
        #pragma unroll
        for (int ar = 0; ar < 8; ++ar) {
            const int row = ((ar & 4) << 3) + (ti << 2) + (ar & 3);
            float4 av0 = ahr[ar][0];
            float4 av1 = ahr[ar][1];
            float4 t20 = *(const float4*)(T2s + row * NN + cA);
            float4 t21 = *(const float4*)(T2s + row * NN + cB);
            float a0, a1, a2, a3, a4, a5, a6, a7;
            unpack2(acc[ar][0], a0, a1); unpack2(acc[ar][1], a2, a3);
            unpack2(acc[ar][2], a4, a5); unpack2(acc[ar][3], a6, a7);
            float o0, o1, o2, o3, o4, o5, o6, o7;
            unpack2(b2t[ar][0], o0, o1); unpack2(b2t[ar][1], o2, o3);
            unpack2(b2t[ar][2], o4, o5); unpack2(b2t[ar][3], o6, o7);
            float4 n0, n1;
            n0.x = a0 - o0 + u1 * av0.x + u2 * t20.x + ((row == cA + 0) ? u0 : 0.0f);
            n0.y = a1 - o1 + u1 * av0.y + u2 * t20.y + ((row == cA + 1) ? u0 : 0.0f);
            n0.z = a2 - o2 + u1 * av0.z + u2 * t20.z + ((row == cA + 2) ? u0 : 0.0f);
            n0.w = a3 - o3 + u1 * av0.w + u2 * t20.w + ((row == cA + 3) ? u0 : 0.0f);
            n1.x = a4 - o4 + u1 * av1.x + u2 * t21.x + ((row == cB + 0) ? u0 : 0.0f);
            n1.y = a5 - o5 + u1 * av1.y + u2 * t21.y + ((row == cB + 1) ? u0 : 0.0f);
            n1.z = a6 - o6 + u1 * av1.z + u2 * t21.z + ((row == cB + 2) ? u0 : 0.0f);
            n1.w = a7 - o7 + u1 * av1.w + u2 * t21.w + ((row == cB + 3) ? u0 : 0.0f);
            *(float4*)(Og + row * NN + cA) = n0;
            *(float4*)(Og + row * NN + cB) = n1;
        }
    }
}

#define SMEM_BYTES ((12288 + 32) * 4)

extern "C" void kernel_launch(void* const* d_in, const int* in_sizes, int n_in,
                              void* d_out, int out_size) {
    const float* x = (const float*)d_in[0];
    float* out = (float*)d_out;
    int nmat = in_sizes[0] / (NN * NN);
    cudaFuncSetAttribute(logm_ps_kernel,
                         cudaFuncAttributeMaxDynamicSharedMemorySize, SMEM_BYTES);
    logm_ps_kernel<<<nmat, 64, SMEM_BYTES>>>(x, out);
}

// round 14
// speedup vs baseline: 1.3688x; 1.0483x over previous
#include <cuda_runtime.h>
#include <cuda_fp16.h>
#include <math.h>

// Batched log(A) for SPD 64x64, degree-19 Chebyshev via Paterson-Stockmeyer
// with s=4, k=5: y = T4(Ahat), p = sum_{i<5} U_i(Ahat) T_i(y),
// U_i = u0 I + u1 A + u2 T2 + u3 T3.  7 matmuls total:
//   T2 = 2A^2-I, T3 = 2A*T2-A, T4 = 2*T2^2-I, 3 Clenshaw steps, final.
// R9 = R8 engine (8x8 split register tiles, FFMA2, 64 thr/matrix) with
// T3 stored fp16 (epilogue-only operand) -> 56KB smem -> 4 blocks/SM.

#define NN 64
#define KTERM 5          // Clenshaw terms in y; degree = 4*KTERM - 1 = 19
typedef unsigned long long ull;

__device__ __forceinline__ ull ffma2(ull a, ull b, ull c) {
    ull d;
    asm("fma.rn.f32x2 %0, %1, %2, %3;" : "=l"(d) : "l"(a), "l"(b), "l"(c));
    return d;
}
__device__ __forceinline__ ull dup2(float a) {
    ull d;
    asm("mov.b64 %0, {%1, %1};" : "=l"(d) : "f"(a));
    return d;
}
__device__ __forceinline__ void unpack2(ull v, float& lo, float& hi) {
    asm("mov.b64 {%0, %1}, %2;" : "=f"(lo), "=f"(hi) : "l"(v));
}
__device__ __forceinline__ ull pack2(float lo, float hi) {
    ull d;
    asm("mov.b64 %0, {%1, %2};" : "=l"(d) : "f"(lo), "f"(hi));
    return d;
}

// acc = M * B over K=64, M symmetric (A-operand read via symmetry).
__device__ __forceinline__ void mm64(unsigned aA, unsigned bA, ull acc[8][4]) {
    #pragma unroll
    for (int ar = 0; ar < 8; ++ar)
        #pragma unroll
        for (int bp = 0; bp < 4; ++bp) acc[ar][bp] = 0ULL;
    #pragma unroll 4
    for (int kk = 0; kk < NN; ++kk) {
        float4 a0, a1;
        asm("ld.shared.v4.f32 {%0,%1,%2,%3}, [%4];"
            : "=f"(a0.x), "=f"(a0.y), "=f"(a0.z), "=f"(a0.w) : "r"(aA));
        asm("ld.shared.v4.f32 {%0,%1,%2,%3}, [%4+128];"
            : "=f"(a1.x), "=f"(a1.y), "=f"(a1.z), "=f"(a1.w) : "r"(aA));
        ull b0, b1v, b2v, b3v;
        asm("ld.shared.v2.u64 {%0,%1}, [%2];"     : "=l"(b0),  "=l"(b1v) : "r"(bA));
        asm("ld.shared.v2.u64 {%0,%1}, [%2+128];" : "=l"(b2v), "=l"(b3v) : "r"(bA));
        ull ad[8];
        ad[0] = dup2(a0.x); ad[1] = dup2(a0.y); ad[2] = dup2(a0.z); ad[3] = dup2(a0.w);
        ad[4] = dup2(a1.x); ad[5] = dup2(a1.y); ad[6] = dup2(a1.z); ad[7] = dup2(a1.w);
        #pragma unroll
        for (int ar = 0; ar < 8; ++ar) {
            acc[ar][0] = ffma2(ad[ar], b0,  acc[ar][0]);
            acc[ar][1] = ffma2(ad[ar], b1v, acc[ar][1]);
            acc[ar][2] = ffma2(ad[ar], b2v, acc[ar][2]);
            acc[ar][3] = ffma2(ad[ar], b3v, acc[ar][3]);
        }
        aA += NN * 4;
        bA += NN * 4;
    }
}

__global__ __launch_bounds__(64, 4)
void logm_ps4_kernel(const float* __restrict__ A, float* __restrict__ Out)
{
    extern __shared__ __align__(16) float sm[];
    float*  M0  = sm;                     // Ahat, later overwritten by Y = T4
    float*  T2s = sm + 4096;              // T2(Ahat), fp32 (matmul operand)
    float*  Bs  = sm + 8192;              // Clenshaw b (in y)
    __half* T3h = (__half*)(sm + 12288);  // T3(Ahat), fp16 (epilogue only)
    float*  us  = sm + 14336;             // 20 folded coefficients u[i][j]=us[4i+j]

    const int tid = threadIdx.x;
    const int mat = blockIdx.x;
    const int ti  = tid >> 3;
    const int tj  = tid & 7;

    const float lo  = 0.095f, hi = 5.15f;
    const float h   = 0.5f * (hi - lo);
    const float mid = 0.5f * (hi + lo);
    const float u   = mid / h;
    const float rho = u + sqrtf(u * u - 1.0f);
    const float alpha = 1.0f / h;

    // ---- Load A -> Ahat = alpha*A - u*I ----
    {
        const float4* Ag = (const float4*)(A + (size_t)mat * (NN * NN));
        #pragma unroll
        for (int r = 0; r < 16; ++r) {
            int q = tid + (r << 6);
            float4 v = Ag[q];
            int i = q >> 4;
            int j = (q & 15) << 2;
            v.x = alpha * v.x - ((j + 0 == i) ? u : 0.0f);
            v.y = alpha * v.y - ((j + 1 == i) ? u : 0.0f);
            v.z = alpha * v.z - ((j + 2 == i) ? u : 0.0f);
            v.w = alpha * v.w - ((j + 3 == i) ? u : 0.0f);
            *(float4*)(M0 + i * NN + j) = v;
        }
    }

    // ---- Thread 0: fold Chebyshev coeffs d_0..d_19 into u[i][j] ----
    // T_{4i+j} = 2 T_j T_{4i} - T_{4i-j}  (descending i; j=1..3)
    if (tid == 0) {
        float d[4 * KTERM];
        d[0] = logf(h * rho * 0.5f);
        float rpw = 1.0f;
        const float ir = 1.0f / rho;
        #pragma unroll
        for (int m = 1; m < 4 * KTERM; ++m) {
            rpw *= ir;
            d[m] = ((m & 1) ? 2.0f : -2.0f) * rpw / (float)m;
        }
        #pragma unroll
        for (int i = KTERM - 1; i >= 1; --i) {
            #pragma unroll
            for (int j = 1; j <= 3; ++j) {
                us[4 * i + j] = 2.0f * d[4 * i + j];
                d[4 * i - j] -= d[4 * i + j];
            }
            us[4 * i] = d[4 * i];
        }
        us[0] = d[0];
        us[1] = d[1];
        us[2] = d[2];
        us[3] = d[3];
    }
    __syncthreads();

    const unsigned sM0 = (unsigned)__cvta_generic_to_shared(M0);
    const unsigned sT2 = (unsigned)__cvta_generic_to_shared(T2s);
    const unsigned sB  = (unsigned)__cvta_generic_to_shared(Bs);
    const unsigned oA  = (unsigned)(ti << 4);
    const unsigned oB  = (unsigned)(tj << 4);
    const int cA = tj << 2;
    const int cB = 32 + (tj << 2);

    // ---- Stash this thread's Ahat tile in registers (epilogue operand) ----
    float4 ahr[8][2];
    #pragma unroll
    for (int ar = 0; ar < 8; ++ar) {
        const int row = ((ar & 4) << 3) + (ti << 2) + (ar & 3);
        ahr[ar][0] = *(const float4*)(M0 + row * NN + cA);
        ahr[ar][1] = *(const float4*)(M0 + row * NN + cB);
    }

    ull acc[8][4];

    // ---- mm1: T2 = 2*Ah*Ah - I ----
    mm64(sM0 + oA, sM0 + oB, acc);
    #pragma unroll
    for (int ar = 0; ar < 8; ++ar) {
        const int row = ((ar & 4) << 3) + (ti << 2) + (ar & 3);
        float a0, a1, a2, a3, a4, a5, a6, a7;
        unpack2(acc[ar][0], a0, a1); unpack2(acc[ar][1], a2, a3);
        unpack2(acc[ar][2], a4, a5); unpack2(acc[ar][3], a6, a7);
        float4 n0, n1;
        n0.x = 2.0f * a0 - ((row == cA + 0) ? 1.0f : 0.0f);
        n0.y = 2.0f * a1 - ((row == cA + 1) ? 1.0f : 0.0f);
        n0.z = 2.0f * a2 - ((row == cA + 2) ? 1.0f : 0.0f);
        n0.w = 2.0f * a3 - ((row == cA + 3) ? 1.0f : 0.0f);
        n1.x = 2.0f * a4 - ((row == cB + 0) ? 1.0f : 0.0f);
        n1.y = 2.0f * a5 - ((row == cB + 1) ? 1.0f : 0.0f);
        n1.z = 2.0f * a6 - ((row == cB + 2) ? 1.0f : 0.0f);
        n1.w = 2.0f * a7 - ((row == cB + 3) ? 1.0f : 0.0f);
        *(float4*)(T2s + row * NN + cA) = n0;
        *(float4*)(T2s + row * NN + cB) = n1;
    }
    __syncthreads();

    // ---- mm2: acc = Ah*T2 ; T3 = 2*acc - Ah -> fp16 T3h ----
    mm64(sM0 + oA, sT2 + oB, acc);
    #pragma unroll
    for (int ar = 0; ar < 8; ++ar) {
        const int row = ((ar & 4) << 3) + (ti << 2) + (ar & 3);
        float4 av0 = ahr[ar][0];
        float4 av1 = ahr[ar][1];
        float a0, a1, a2, a3, a4, a5, a6, a7;
        unpack2(acc[ar][0], a0, a1); unpack2(acc[ar][1], a2, a3);
        unpack2(acc[ar][2], a4, a5); unpack2(acc[ar][3], a6, a7);
        __half2* ThA = (__half2*)(T3h + row * NN + cA);
        __half2* ThB = (__half2*)(T3h + row * NN + cB);
        ThA[0] = __floats2half2_rn(2.0f * a0 - av0.x, 2.0f * a1 - av0.y);
        ThA[1] = __floats2half2_rn(2.0f * a2 - av0.z, 2.0f * a3 - av0.w);
        ThB[0] = __floats2half2_rn(2.0f * a4 - av1.x, 2.0f * a5 - av1.y);
        ThB[1] = __floats2half2_rn(2.0f * a6 - av1.z, 2.0f * a7 - av1.w);
    }
    __syncthreads();   // all mm2 reads of M0 done (Y overwrite next)

    // ---- mm3: acc = T2*T2 ; Y = 2*acc - I -> M0 ;
    //      B = U_4 = u0 I + u1 Ah + u2 T2 + u3 T3 -> Bs ----
    mm64(sT2 + oA, sT2 + oB, acc);
    {
        const float u40 = us[4 * (KTERM - 1) + 0];
        const float u41 = us[4 * (KTERM - 1) + 1];
        const float u42 = us[4 * (KTERM - 1) + 2];
        const float u43 = us[4 * (KTERM - 1) + 3];
        #pragma unroll
        for (int ar = 0; ar < 8; ++ar) {
            const int row = ((ar & 4) << 3) + (ti << 2) + (ar & 3);
            float4 av0 = ahr[ar][0];
            float4 av1 = ahr[ar][1];
            float4 t20 = *(const float4*)(T2s + row * NN + cA);
            float4 t21 = *(const float4*)(T2s + row * NN + cB);
            const __half2* ThA = (const __half2*)(T3h + row * NN + cA);
            const __half2* ThB = (const __half2*)(T3h + row * NN + cB);
            float2 q0 = __half22float2(ThA[0]);
            float2 q1 = __half22float2(ThA[1]);
            float2 q2 = __half22float2(ThB[0]);
            float2 q3 = __half22float2(ThB[1]);
            float a0, a1, a2, a3, a4, a5, a6, a7;
            unpack2(acc[ar][0], a0, a1); unpack2(acc[ar][1], a2, a3);
            unpack2(acc[ar][2], a4, a5); unpack2(acc[ar][3], a6, a7);
            float4 y0, y1;
            y0.x = 2.0f * a0 - ((row == cA + 0) ? 1.0f : 0.0f);
            y0.y = 2.0f * a1 - ((row == cA + 1) ? 1.0f : 0.0f);
            y0.z = 2.0f * a2 - ((row == cA + 2) ? 1.0f : 0.0f);
            y0.w = 2.0f * a3 - ((row == cA + 3) ? 1.0f : 0.0f);
            y1.x = 2.0f * a4 - ((row == cB + 0) ? 1.0f : 0.0f);
            y1.y = 2.0f * a5 - ((row == cB + 1) ? 1.0f : 0.0f);
            y1.z = 2.0f * a6 - ((row == cB + 2) ? 1.0f : 0.0f);
            y1.w = 2.0f * a7 - ((row == cB + 3) ? 1.0f : 0.0f);
            *(float4*)(M0 + row * NN + cA) = y0;
            *(float4*)(M0 + row * NN + cB) = y1;
            float4 b0, b1;
            b0.x = u41 * av0.x + u42 * t20.x + u43 * q0.x + ((row == cA + 0) ? u40 : 0.0f);
            b0.y = u41 * av0.y + u42 * t20.y + u43 * q0.y + ((row == cA + 1) ? u40 : 0.0f);
            b0.z = u41 * av0.z + u42 * t20.z + u43 * q1.x + ((row == cA + 2) ? u40 : 0.0f);
            b0.w = u41 * av0.w + u42 * t20.w + u43 * q1.y + ((row == cA + 3) ? u40 : 0.0f);
            b1.x = u41 * av1.x + u42 * t21.x + u43 * q2.x + ((row == cB + 0) ? u40 : 0.0f);
            b1.y = u41 * av1.y + u42 * t21.y + u43 * q2.y + ((row == cB + 1) ? u40 : 0.0f);
            b1.z = u41 * av1.z + u42 * t21.z + u43 * q3.x + ((row == cB + 2) ? u40 : 0.0f);
            b1.w = u41 * av1.w + u42 * t21.w + u43 * q3.y + ((row == cB + 3) ? u40 : 0.0f);
            *(float4*)(Bs + row * NN + cA) = b0;
            *(float4*)(Bs + row * NN + cB) = b1;
        }
    }
    ull b2t[8][4];
    #pragma unroll
    for (int ar = 0; ar < 8; ++ar)
        #pragma unroll
        for (int bp = 0; bp < 4; ++bp) b2t[ar][bp] = 0ULL;
    __syncthreads();

    // ---- Clenshaw in y: i = 3..1  (M0 holds Y) ----
    for (int i = KTERM - 2; i >= 1; --i) {
        const float u0 = us[4 * i + 0];
        const float u1 = us[4 * i + 1];
        const float u2 = us[4 * i + 2];
        const float u3 = us[4 * i + 3];
        mm64(sM0 + oA, sB + oB, acc);
        __syncthreads();
        #pragma unroll
        for (int ar = 0; ar < 8; ++ar) {
            const int row = ((ar & 4) << 3) + (ti << 2) + (ar & 3);
            float* Bp = Bs + row * NN;
            float4 t0 = *(const float4*)(Bp + cA);     // old b1 -> next b2
            float4 t1 = *(const float4*)(Bp + cB);
            float4 av0 = ahr[ar][0];
            float4 av1 = ahr[ar][1];
            float4 t20 = *(const float4*)(T2s + row * NN + cA);
            float4 t21 = *(const float4*)(T2s + row * NN + cB);
            const __half2* ThA = (const __half2*)(T3h + row * NN + cA);
            const __half2* ThB = (const __half2*)(T3h + row * NN + cB);
            float2 q0 = __half22float2(ThA[0]);
            float2 q1 = __half22float2(ThA[1]);
            float2 q2 = __half22float2(ThB[0]);
            float2 q3 = __half22float2(ThB[1]);
            float a0, a1, a2, a3, a4, a5, a6, a7;
            unpack2(acc[ar][0], a0, a1); unpack2(acc[ar][1], a2, a3);
            unpack2(acc[ar][2], a4, a5); unpack2(acc[ar][3], a6, a7);
            float o0, o1, o2, o3, o4, o5, o6, o7;
            unpack2(b2t[ar][0], o0, o1); unpack2(b2t[ar][1], o2, o3);
            unpack2(b2t[ar][2], o4, o5); unpack2(b2t[ar][3], o6, o7);
            float4 n0, n1;
            n0.x = 2.0f * a0 - o0 + u1 * av0.x + u2 * t20.x + u3 * q0.x + ((row == cA + 0) ? u0 : 0.0f);
            n0.y = 2.0f * a1 - o1 + u1 * av0.y + u2 * t20.y + u3 * q0.y + ((row == cA + 1) ? u0 : 0.0f);
            n0.z = 2.0f * a2 - o2 + u1 * av0.z + u2 * t20.z + u3 * q1.x + ((row == cA + 2) ? u0 : 0.0f);
            n0.w = 2.0f * a3 - o3 + u1 * av0.w + u2 * t20.w + u3 * q1.y + ((row == cA + 3) ? u0 : 0.0f);
            n1.x = 2.0f * a4 - o4 + u1 * av1.x + u2 * t21.x + u3 * q2.x + ((row == cB + 0) ? u0 : 0.0f);
            n1.y = 2.0f * a5 - o5 + u1 * av1.y + u2 * t21.y + u3 * q2.y + ((row == cB + 1) ? u0 : 0.0f);
            n1.z = 2.0f * a6 - o6 + u1 * av1.z + u2 * t21.z + u3 * q3.x + ((row == cB + 2) ? u0 : 0.0f);
            n1.w = 2.0f * a7 - o7 + u1 * av1.w + u2 * t21.w + u3 * q3.y + ((row == cB + 3) ? u0 : 0.0f);
            *(float4*)(Bp + cA) = n0;
            *(float4*)(Bp + cB) = n1;
            b2t[ar][0] = pack2(t0.x, t0.y);
            b2t[ar][1] = pack2(t0.z, t0.w);
            b2t[ar][2] = pack2(t1.x, t1.y);
            b2t[ar][3] = pack2(t1.z, t1.w);
        }
        __syncthreads();
    }

    // ---- Final: out = U_0 + y*b1 - b2 ----
    {
        const float u0 = us[0];
        const float u1 = us[1];
        const float u2 = us[2];
        const float u3 = us[3];
        mm64(sM0 + oA, sB + oB, acc);
        float* Og = Out + (size_t)mat * (NN * NN);
        #pragma unroll
        for (int ar = 0; ar < 8; ++ar) {
            const int row = ((ar & 4) << 3) + (ti << 2) + (ar & 3);
            float4 av0 = ahr[ar][0];
            float4 av1 = ahr[ar][1];
            float4 t20 = *(const float4*)(T2s + row * NN + cA);
            float4 t21 = *(const float4*)(T2s + row * NN + cB);
            const __half2* ThA = (const __half2*)(T3h + row * NN + cA);
            const __half2* ThB = (const __half2*)(T3h + row * NN + cB);
            float2 q0 = __half22float2(ThA[0]);
            float2 q1 = __half22float2(ThA[1]);
            float2 q2 = __half22float2(ThB[0]);
            float2 q3 = __half22float2(ThB[1]);
            float a0, a1, a2, a3, a4, a5, a6, a7;
            unpack2(acc[ar][0], a0, a1); unpack2(acc[ar][1], a2, a3);
            unpack2(acc[ar][2], a4, a5); unpack2(acc[ar][3], a6, a7);
            float o0, o1, o2, o3, o4, o5, o6, o7;
            unpack2(b2t[ar][0], o0, o1); unpack2(b2t[ar][1], o2, o3);
            unpack2(b2t[ar][2], o4, o5); unpack2(b2t[ar][3], o6, o7);
            float4 n0, n1;
            n0.x = a0 - o0 + u1 * av0.x + u2 * t20.x + u3 * q0.x + ((row == cA + 0) ? u0 : 0.0f);
            n0.y = a1 - o1 + u1 * av0.y + u2 * t20.y + u3 * q0.y + ((row == cA + 1) ? u0 : 0.0f);
            n0.z = a2 - o2 + u1 * av0.z + u2 * t20.z + u3 * q1.x + ((row == cA + 2) ? u0 : 0.0f);
            n0.w = a3 - o3 + u1 * av0.w + u2 * t20.w + u3 * q1.y + ((row == cA + 3) ? u0 : 0.0f);
            n1.x = a4 - o4 + u1 * av1.x + u2 * t21.x + u3 * q2.x + ((row == cB + 0) ? u0 : 0.0f);
            n1.y = a5 - o5 + u1 * av1.y + u2 * t21.y + u3 * q2.y + ((row == cB + 1) ? u0 : 0.0f);
            n1.z = a6 - o6 + u1 * av1.z + u2 * t21.z + u3 * q3.x + ((row == cB + 2) ? u0 : 0.0f);
            n1.w = a7 - o7 + u1 * av1.w + u2 * t21.w + u3 * q3.y + ((row == cB + 3) ? u0 : 0.0f);
            *(float4*)(Og + row * NN + cA) = n0;
            *(float4*)(Og + row * NN + cB) = n1;
        }
    }
}

#define SMEM_BYTES ((14336 + 24) * 4)

extern "C" void kernel_launch(void* const* d_in, const int* in_sizes, int n_in,
                              void* d_out, int out_size) {
    const float* x = (const float*)d_in[0];
    float* out = (float*)d_out;
    int nmat = in_sizes[0] / (NN * NN);
    cudaFuncSetAttribute(logm_ps4_kernel,
                         cudaFuncAttributeMaxDynamicSharedMemorySize, SMEM_BYTES);
    logm_ps4_kernel<<<nmat, 64, SMEM_BYTES>>>(x, out);
}

// round 15
// speedup vs baseline: 1.4499x; 1.0592x over previous
#include <cuda_runtime.h>
#include <cuda_fp16.h>
#include <math.h>

// Batched log(A) for SPD 64x64, degree-19 Chebyshev via Paterson-Stockmeyer
// with s=4, k=5: y = T4(Ahat), p = sum_{i<5} U_i(Ahat) T_i(y),
// U_i = u0 I + u1 A + u2 T2 + u3 T3.  7 matmuls.
// R10 = R9 with the folded coefficients passed as a kernel-argument struct
// (constant memory) instead of a smem array -> smem exactly 56KB -> 4 blocks/SM.

#define NN 64
#define KTERM 5          // degree = 4*KTERM - 1 = 19
typedef unsigned long long ull;

struct Coef { float us[4 * KTERM]; float alpha, u; };

__device__ __forceinline__ ull ffma2(ull a, ull b, ull c) {
    ull d;
    asm("fma.rn.f32x2 %0, %1, %2, %3;" : "=l"(d) : "l"(a), "l"(b), "l"(c));
    return d;
}
__device__ __forceinline__ ull dup2(float a) {
    ull d;
    asm("mov.b64 %0, {%1, %1};" : "=l"(d) : "f"(a));
    return d;
}
__device__ __forceinline__ void unpack2(ull v, float& lo, float& hi) {
    asm("mov.b64 {%0, %1}, %2;" : "=f"(lo), "=f"(hi) : "l"(v));
}
__device__ __forceinline__ ull pack2(float lo, float hi) {
    ull d;
    asm("mov.b64 %0, {%1, %2};" : "=l"(d) : "f"(lo), "f"(hi));
    return d;
}

// acc = M * B over K=64, M symmetric (A-operand read via symmetry).
__device__ __forceinline__ void mm64(unsigned aA, unsigned bA, ull acc[8][4]) {
    #pragma unroll
    for (int ar = 0; ar < 8; ++ar)
        #pragma unroll
        for (int bp = 0; bp < 4; ++bp) acc[ar][bp] = 0ULL;
    #pragma unroll 4
    for (int kk = 0; kk < NN; ++kk) {
        float4 a0, a1;
        asm("ld.shared.v4.f32 {%0,%1,%2,%3}, [%4];"
            : "=f"(a0.x), "=f"(a0.y), "=f"(a0.z), "=f"(a0.w) : "r"(aA));
        asm("ld.shared.v4.f32 {%0,%1,%2,%3}, [%4+128];"
            : "=f"(a1.x), "=f"(a1.y), "=f"(a1.z), "=f"(a1.w) : "r"(aA));
        ull b0, b1v, b2v, b3v;
        asm("ld.shared.v2.u64 {%0,%1}, [%2];"     : "=l"(b0),  "=l"(b1v) : "r"(bA));
        asm("ld.shared.v2.u64 {%0,%1}, [%2+128];" : "=l"(b2v), "=l"(b3v) : "r"(bA));
        ull ad[8];
        ad[0] = dup2(a0.x); ad[1] = dup2(a0.y); ad[2] = dup2(a0.z); ad[3] = dup2(a0.w);
        ad[4] = dup2(a1.x); ad[5] = dup2(a1.y); ad[6] = dup2(a1.z); ad[7] = dup2(a1.w);
        #pragma unroll
        for (int ar = 0; ar < 8; ++ar) {
            acc[ar][0] = ffma2(ad[ar], b0,  acc[ar][0]);
            acc[ar][1] = ffma2(ad[ar], b1v, acc[ar][1]);
            acc[ar][2] = ffma2(ad[ar], b2v, acc[ar][2]);
            acc[ar][3] = ffma2(ad[ar], b3v, acc[ar][3]);
        }
        aA += NN * 4;
        bA += NN * 4;
    }
}

__global__ __launch_bounds__(64, 4)
void logm_ps4_kernel(const float* __restrict__ A, float* __restrict__ Out,
                     const Coef cf)
{
    extern __shared__ __align__(16) float sm[];
    float*  M0  = sm;                     // Ahat, later overwritten by Y = T4
    float*  T2s = sm + 4096;              // T2(Ahat), fp32 (matmul operand)
    float*  Bs  = sm + 8192;              // Clenshaw b (in y)
    __half* T3h = (__half*)(sm + 12288);  // T3(Ahat), fp16 (epilogue only)

    const int tid = threadIdx.x;
    const int mat = blockIdx.x;
    const int ti  = tid >> 3;
    const int tj  = tid & 7;

    const float alpha = cf.alpha;
    const float u     = cf.u;

    // ---- Load A -> Ahat = alpha*A - u*I ----
    {
        const float4* Ag = (const float4*)(A + (size_t)mat * (NN * NN));
        #pragma unroll
        for (int r = 0; r < 16; ++r) {
            int q = tid + (r << 6);
            float4 v = Ag[q];
            int i = q >> 4;
            int j = (q & 15) << 2;
            v.x = alpha * v.x - ((j + 0 == i) ? u : 0.0f);
            v.y = alpha * v.y - ((j + 1 == i) ? u : 0.0f);
            v.z = alpha * v.z - ((j + 2 == i) ? u : 0.0f);
            v.w = alpha * v.w - ((j + 3 == i) ? u : 0.0f);
            *(float4*)(M0 + i * NN + j) = v;
        }
    }
    __syncthreads();

    const unsigned sM0 = (unsigned)__cvta_generic_to_shared(M0);
    const unsigned sT2 = (unsigned)__cvta_generic_to_shared(T2s);
    const unsigned sB  = (unsigned)__cvta_generic_to_shared(Bs);
    const unsigned oA  = (unsigned)(ti << 4);
    const unsigned oB  = (unsigned)(tj << 4);
    const int cA = tj << 2;
    const int cB = 32 + (tj << 2);

    // ---- Stash this thread's Ahat tile in registers (epilogue operand) ----
    float4 ahr[8][2];
    #pragma unroll
    for (int ar = 0; ar < 8; ++ar) {
        const int row = ((ar & 4) << 3) + (ti << 2) + (ar & 3);
        ahr[ar][0] = *(const float4*)(M0 + row * NN + cA);
        ahr[ar][1] = *(const float4*)(M0 + row * NN + cB);
    }

    ull acc[8][4];

    // ---- mm1: T2 = 2*Ah*Ah - I ----
    mm64(sM0 + oA, sM0 + oB, acc);
    #pragma unroll
    for (int ar = 0; ar < 8; ++ar) {
        const int row = ((ar & 4) << 3) + (ti << 2) + (ar & 3);
        float a0, a1, a2, a3, a4, a5, a6, a7;
        unpack2(acc[ar][0], a0, a1); unpack2(acc[ar][1], a2, a3);
        unpack2(acc[ar][2], a4, a5); unpack2(acc[ar][3], a6, a7);
        float4 n0, n1;
        n0.x = 2.0f * a0 - ((row == cA + 0) ? 1.0f : 0.0f);
        n0.y = 2.0f * a1 - ((row == cA + 1) ? 1.0f : 0.0f);
        n0.z = 2.0f * a2 - ((row == cA + 2) ? 1.0f : 0.0f);
        n0.w = 2.0f * a3 - ((row == cA + 3) ? 1.0f : 0.0f);
        n1.x = 2.0f * a4 - ((row == cB + 0) ? 1.0f : 0.0f);
        n1.y = 2.0f * a5 - ((row == cB + 1) ? 1.0f : 0.0f);
        n1.z = 2.0f * a6 - ((row == cB + 2) ? 1.0f : 0.0f);
        n1.w = 2.0f * a7 - ((row == cB + 3) ? 1.0f : 0.0f);
        *(float4*)(T2s + row * NN + cA) = n0;
        *(float4*)(T2s + row * NN + cB) = n1;
    }
    __syncthreads();

    // ---- mm2: acc = Ah*T2 ; T3 = 2*acc - Ah -> fp16 T3h ----
    mm64(sM0 + oA, sT2 + oB, acc);
    #pragma unroll
    for (int ar = 0; ar < 8; ++ar) {
        const int row = ((ar & 4) << 3) + (ti << 2) + (ar & 3);
        float4 av0 = ahr[ar][0];
        float4 av1 = ahr[ar][1];
        float a0, a1, a2, a3, a4, a5, a6, a7;
        unpack2(acc[ar][0], a0, a1); unpack2(acc[ar][1], a2, a3);
        unpack2(acc[ar][2], a4, a5); unpack2(acc[ar][3], a6, a7);
        __half2* ThA = (__half2*)(T3h + row * NN + cA);
        __half2* ThB = (__half2*)(T3h + row * NN + cB);
        ThA[0] = __floats2half2_rn(2.0f * a0 - av0.x, 2.0f * a1 - av0.y);
        ThA[1] = __floats2half2_rn(2.0f * a2 - av0.z, 2.0f * a3 - av0.w);
        ThB[0] = __floats2half2_rn(2.0f * a4 - av1.x, 2.0f * a5 - av1.y);
        ThB[1] = __floats2half2_rn(2.0f * a6 - av1.z, 2.0f * a7 - av1.w);
    }
    __syncthreads();   // all mm2 reads of M0 done (Y overwrite next)

    // ---- mm3: acc = T2*T2 ; Y = 2*acc - I -> M0 ;
    //      B = U_4 = u0 I + u1 Ah + u2 T2 + u3 T3 -> Bs ----
    mm64(sT2 + oA, sT2 + oB, acc);
    {
        const float u40 = cf.us[4 * (KTERM - 1) + 0];
        const float u41 = cf.us[4 * (KTERM - 1) + 1];
        const float u42 = cf.us[4 * (KTERM - 1) + 2];
        const float u43 = cf.us[4 * (KTERM - 1) + 3];
        #pragma unroll
        for (int ar = 0; ar < 8; ++ar) {
            const int row = ((ar & 4) << 3) + (ti << 2) + (ar & 3);
            float4 av0 = ahr[ar][0];
            float4 av1 = ahr[ar][1];
            float4 t20 = *(const float4*)(T2s + row * NN + cA);
            float4 t21 = *(const float4*)(T2s + row * NN + cB);
            const __half2* ThA = (const __half2*)(T3h + row * NN + cA);
            const __half2* ThB = (const __half2*)(T3h + row * NN + cB);
            float2 q0 = __half22float2(ThA[0]);
            float2 q1 = __half22float2(ThA[1]);
            float2 q2 = __half22float2(ThB[0]);
            float2 q3 = __half22float2(ThB[1]);
            float a0, a1, a2, a3, a4, a5, a6, a7;
            unpack2(acc[ar][0], a0, a1); unpack2(acc[ar][1], a2, a3);
            unpack2(acc[ar][2], a4, a5); unpack2(acc[ar][3], a6, a7);
            float4 y0, y1;
            y0.x = 2.0f * a0 - ((row == cA + 0) ? 1.0f : 0.0f);
            y0.y = 2.0f * a1 - ((row == cA + 1) ? 1.0f : 0.0f);
            y0.z = 2.0f * a2 - ((row == cA + 2) ? 1.0f : 0.0f);
            y0.w = 2.0f * a3 - ((row == cA + 3) ? 1.0f : 0.0f);
            y1.x = 2.0f * a4 - ((row == cB + 0) ? 1.0f : 0.0f);
            y1.y = 2.0f * a5 - ((row == cB + 1) ? 1.0f : 0.0f);
            y1.z = 2.0f * a6 - ((row == cB + 2) ? 1.0f : 0.0f);
            y1.w = 2.0f * a7 - ((row == cB + 3) ? 1.0f : 0.0f);
            *(float4*)(M0 + row * NN + cA) = y0;
            *(float4*)(M0 + row * NN + cB) = y1;
            float4 b0, b1;
            b0.x = u41 * av0.x + u42 * t20.x + u43 * q0.x + ((row == cA + 0) ? u40 : 0.0f);
            b0.y = u41 * av0.y + u42 * t20.y + u43 * q0.y + ((row == cA + 1) ? u40 : 0.0f);
            b0.z = u41 * av0.z + u42 * t20.z + u43 * q1.x + ((row == cA + 2) ? u40 : 0.0f);
            b0.w = u41 * av0.w + u42 * t20.w + u43 * q1.y + ((row == cA + 3) ? u40 : 0.0f);
            b1.x = u41 * av1.x + u42 * t21.x + u43 * q2.x + ((row == cB + 0) ? u40 : 0.0f);
            b1.y = u41 * av1.y + u42 * t21.y + u43 * q2.y + ((row == cB + 1) ? u40 : 0.0f);
            b1.z = u41 * av1.z + u42 * t21.z + u43 * q3.x + ((row == cB + 2) ? u40 : 0.0f);
            b1.w = u41 * av1.w + u42 * t21.w + u43 * q3.y + ((row == cB + 3) ? u40 : 0.0f);
            *(float4*)(Bs + row * NN + cA) = b0;
            *(float4*)(Bs + row * NN + cB) = b1;
        }
    }
    ull b2t[8][4];
    #pragma unroll
    for (int ar = 0; ar < 8; ++ar)
        #pragma unroll
        for (int bp = 0; bp < 4; ++bp) b2t[ar][bp] = 0ULL;
    __syncthreads();

    // ---- Clenshaw in y: i = 3..1  (M0 holds Y) ----
    #pragma unroll
    for (int i = KTERM - 2; i >= 1; --i) {
        const float u0 = cf.us[4 * i + 0];
        const float u1 = cf.us[4 * i + 1];
        const float u2 = cf.us[4 * i + 2];
        const float u3 = cf.us[4 * i + 3];
        mm64(sM0 + oA, sB + oB, acc);
        __syncthreads();
        #pragma unroll
        for (int ar = 0; ar < 8; ++ar) {
            const int row = ((ar & 4) << 3) + (ti << 2) + (ar & 3);
            float* Bp = Bs + row * NN;
            float4 t0 = *(const float4*)(Bp + cA);     // old b1 -> next b2
            float4 t1 = *(const float4*)(Bp + cB);
            float4 av0 = ahr[ar][0];
            float4 av1 = ahr[ar][1];
            float4 t20 = *(const float4*)(T2s + row * NN + cA);
            float4 t21 = *(const float4*)(T2s + row * NN + cB);
            const __half2* ThA = (const __half2*)(T3h + row * NN + cA);
            const __half2* ThB = (const __half2*)(T3h + row * NN + cB);
            float2 q0 = __half22float2(ThA[0]);
            float2 q1 = __half22float2(ThA[1]);
            float2 q2 = __half22float2(ThB[0]);
            float2 q3 = __half22float2(ThB[1]);
            float a0, a1, a2, a3, a4, a5, a6, a7;
            unpack2(acc[ar][0], a0, a1); unpack2(acc[ar][1], a2, a3);
            unpack2(acc[ar][2], a4, a5); unpack2(acc[ar][3], a6, a7);
            float o0, o1, o2, o3, o4, o5, o6, o7;
            unpack2(b2t[ar][0], o0, o1); unpack2(b2t[ar][1], o2, o3);
            unpack2(b2t[ar][2], o4, o5); unpack2(b2t[ar][3], o6, o7);
            float4 n0, n1;
            n0.x = 2.0f * a0 - o0 + u1 * av0.x + u2 * t20.x + u3 * q0.x + ((row == cA + 0) ? u0 : 0.0f);
            n0.y = 2.0f * a1 - o1 + u1 * av0.y + u2 * t20.y + u3 * q0.y + ((row == cA + 1) ? u0 : 0.0f);
            n0.z = 2.0f * a2 - o2 + u1 * av0.z + u2 * t20.z + u3 * q1.x + ((row == cA + 2) ? u0 : 0.0f);
            n0.w = 2.0f * a3 - o3 + u1 * av0.w + u2 * t20.w + u3 * q1.y + ((row == cA + 3) ? u0 : 0.0f);
            n1.x = 2.0f * a4 - o4 + u1 * av1.x + u2 * t21.x + u3 * q2.x + ((row == cB + 0) ? u0 : 0.0f);
            n1.y = 2.0f * a5 - o5 + u1 * av1.y + u2 * t21.y + u3 * q2.y + ((row == cB + 1) ? u0 : 0.0f);
            n1.z = 2.0f * a6 - o6 + u1 * av1.z + u2 * t21.z + u3 * q3.x + ((row == cB + 2) ? u0 : 0.0f);
            n1.w = 2.0f * a7 - o7 + u1 * av1.w + u2 * t21.w + u3 * q3.y + ((row == cB + 3) ? u0 : 0.0f);
            *(float4*)(Bp + cA) = n0;
            *(float4*)(Bp + cB) = n1;
            b2t[ar][0] = pack2(t0.x, t0.y);
            b2t[ar][1] = pack2(t0.z, t0.w);
            b2t[ar][2] = pack2(t1.x, t1.y);
            b2t[ar][3] = pack2(t1.z, t1.w);
        }
        __syncthreads();
    }

    // ---- Final: out = U_0 + y*b1 - b2 ----
    {
        const float u0 = cf.us[0];
        const float u1 = cf.us[1];
        const float u2 = cf.us[2];
        const float u3 = cf.us[3];
        mm64(sM0 + oA, sB + oB, acc);
        float* Og = Out + (size_t)mat * (NN * NN);
        #pragma unroll
        for (int ar = 0; ar < 8; ++ar) {
            const int row = ((ar & 4) << 3) + (ti << 2) + (ar & 3);
            float4 av0 = ahr[ar][0];
            float4 av1 = ahr[ar][1];
            float4 t20 = *(const float4*)(T2s + row * NN + cA);
            float4 t21 = *(const float4*)(T2s + row * NN + cB);
            const __half2* ThA = (const __half2*)(T3h + row * NN + cA);
            const __half2* ThB = (const __half2*)(T3h + row * NN + cB);
            float2 q0 = __half22float2(ThA[0]);
            float2 q1 = __half22float2(ThA[1]);
            float2 q2 = __half22float2(ThB[0]);
            float2 q3 = __half22float2(ThB[1]);
            float a0, a1, a2, a3, a4, a5, a6, a7;
            unpack2(acc[ar][0], a0, a1); unpack2(acc[ar][1], a2, a3);
            unpack2(acc[ar][2], a4, a5); unpack2(acc[ar][3], a6, a7);
            float o0, o1, o2, o3, o4, o5, o6, o7;
            unpack2(b2t[ar][0], o0, o1); unpack2(b2t[ar][1], o2, o3);
            unpack2(b2t[ar][2], o4, o5); unpack2(b2t[ar][3], o6, o7);
            float4 n0, n1;
            n0.x = a0 - o0 + u1 * av0.x + u2 * t20.x + u3 * q0.x + ((row == cA + 0) ? u0 : 0.0f);
            n0.y = a1 - o1 + u1 * av0.y + u2 * t20.y + u3 * q0.y + ((row == cA + 1) ? u0 : 0.0f);
            n0.z = a2 - o2 + u1 * av0.z + u2 * t20.z + u3 * q1.x + ((row == cA + 2) ? u0 : 0.0f);
            n0.w = a3 - o3 + u1 * av0.w + u2 * t20.w + u3 * q1.y + ((row == cA + 3) ? u0 : 0.0f);
            n1.x = a4 - o4 + u1 * av1.x + u2 * t21.x + u3 * q2.x + ((row == cB + 0) ? u0 : 0.0f);
            n1.y = a5 - o5 + u1 * av1.y + u2 * t21.y + u3 * q2.y + ((row == cB + 1) ? u0 : 0.0f);
            n1.z = a6 - o6 + u1 * av1.z + u2 * t21.z + u3 * q3.x + ((row == cB + 2) ? u0 : 0.0f);
            n1.w = a7 - o7 + u1 * av1.w + u2 * t21.w + u3 * q3.y + ((row == cB + 3) ? u0 : 0.0f);
            *(float4*)(Og + row * NN + cA) = n0;
            *(float4*)(Og + row * NN + cB) = n1;
        }
    }
}

#define SMEM_BYTES (14336 * 4)

extern "C" void kernel_launch(void* const* d_in, const int* in_sizes, int n_in,
                              void* d_out, int out_size) {
    const float* x = (const float*)d_in[0];
    float* out = (float*)d_out;
    int nmat = in_sizes[0] / (NN * NN);

    // Host-side coefficient fold (double precision).
    const double lo = 0.095, hi = 5.15;
    const double h   = 0.5 * (hi - lo);
    const double mid = 0.5 * (hi + lo);
    const double uu  = mid / h;
    const double rho = uu + sqrt(uu * uu - 1.0);
    double d[4 * KTERM];
    d[0] = log(h * rho * 0.5);
    double rpw = 1.0;
    for (int m = 1; m < 4 * KTERM; ++m) {
        rpw /= rho;
        d[m] = ((m & 1) ? 2.0 : -2.0) * rpw / (double)m;
    }
    Coef cf;
    for (int i = KTERM - 1; i >= 1; --i) {
        for (int j = 1; j <= 3; ++j) {
            cf.us[4 * i + j] = (float)(2.0 * d[4 * i + j]);
            d[4 * i - j] -= d[4 * i + j];
        }
        cf.us[4 * i] = (float)d[4 * i];
    }
    cf.us[0] = (float)d[0];
    cf.us[1] = (float)d[1];
    cf.us[2] = (float)d[2];
    cf.us[3] = (float)d[3];
    cf.alpha = (float)(1.0 / h);
    cf.u     = (float)uu;

    cudaFuncSetAttribute(logm_ps4_kernel,
                         cudaFuncAttributeMaxDynamicSharedMemorySize, SMEM_BYTES);
    logm_ps4_kernel<<<nmat, 64, SMEM_BYTES>>>(x, out, cf);
}